// round 1
// baseline (speedup 1.0000x reference)
#include <cuda_runtime.h>
#include <cuda_bf16.h>
#include <math.h>

// Problem constants (fixed by the dataset)
#define NN   30000      // nodes
#define NE   60000      // edges
#define FEAT 256
#define HID  1024
#define OUTD 256
#define RANK 64

// ---------------- scratch (device globals; no allocation allowed) ----------------
__device__ float g_emb_new [NN * RANK];      // 7.7 MB
__device__ float g_hidden  [NN * HID];       // 123 MB
__device__ float g_emb_new2[NN * OUTD];      // 30.7 MB
__device__ float g_residual[NN * OUTD];      // 30.7 MB
__device__ float g_tee     [NE * 4 * RANK];  // 61.4 MB  tanh(ee) per (edge,slot)
__device__ float g_esum2   [NE * OUTD];      // 61.4 MB  relu(sum emb_new2)
__device__ float g_nodeacc [NN * OUTD];      // 30.7 MB

// ---------------- generic fp32 tiled GEMM: C = act(A[MxK] @ B[KxN] + bias (+ biasRow)) ----------------
// 128x128 block tile, BK=8, 256 threads, 8x8 microtile per thread.
#define BM 128
#define BN 128
#define BKK 8
#define TM 8
#define TN 8

__global__ __launch_bounds__(256, 2)
void gemm_kernel(const float* __restrict__ A, const float* __restrict__ B,
                 const float* __restrict__ bias, const float* __restrict__ biasRow,
                 float* __restrict__ C, int M, int N, int K, int doRelu)
{
    __shared__ float As[BKK][BM];
    __shared__ float Bs[BKK][BN];

    const int tid = threadIdx.x;
    const int tx = tid % 16;   // N direction
    const int ty = tid / 16;   // M direction
    const int rowBase = blockIdx.y * BM;
    const int colBase = blockIdx.x * BN;

    float acc[TM][TN];
    #pragma unroll
    for (int i = 0; i < TM; i++)
        #pragma unroll
        for (int j = 0; j < TN; j++) acc[i][j] = 0.f;

    // A-tile load mapping: 128 rows x 8 k-cols, each thread one float4 along K
    const int aRow = tid >> 1;          // 0..127
    const int aCol = (tid & 1) * 4;     // 0 or 4
    // B-tile load mapping: 8 k-rows x 128 n-cols, each thread one float4 along N
    const int bRow = tid >> 5;          // 0..7
    const int bCol = (tid & 31) * 4;    // 0..124

    for (int k0 = 0; k0 < K; k0 += BKK) {
        int gr = rowBase + aRow;
        float4 av = make_float4(0.f, 0.f, 0.f, 0.f);
        if (gr < M) av = *(const float4*)(A + (size_t)gr * K + k0 + aCol);
        As[aCol + 0][aRow] = av.x;
        As[aCol + 1][aRow] = av.y;
        As[aCol + 2][aRow] = av.z;
        As[aCol + 3][aRow] = av.w;

        int gc = colBase + bCol;
        float4 bv = make_float4(0.f, 0.f, 0.f, 0.f);
        if (gc < N) bv = *(const float4*)(B + (size_t)(k0 + bRow) * N + gc);
        *(float4*)&Bs[bRow][bCol] = bv;

        __syncthreads();

        #pragma unroll
        for (int kk = 0; kk < BKK; kk++) {
            float aF[TM], bF[TN];
            #pragma unroll
            for (int i = 0; i < TM; i++) aF[i] = As[kk][ty * TM + i];
            #pragma unroll
            for (int j = 0; j < TN; j++) bF[j] = Bs[kk][tx * TN + j];
            #pragma unroll
            for (int i = 0; i < TM; i++)
                #pragma unroll
                for (int j = 0; j < TN; j++)
                    acc[i][j] += aF[i] * bF[j];
        }
        __syncthreads();
    }

    #pragma unroll
    for (int i = 0; i < TM; i++) {
        int row = rowBase + ty * TM + i;
        if (row >= M) continue;
        #pragma unroll
        for (int j = 0; j < TN; j++) {
            int col = colBase + tx * TN + j;
            if (col >= N) continue;
            float v = acc[i][j] + bias[col];
            if (biasRow) v += biasRow[col];
            if (doRelu) v = fmaxf(v, 0.f);
            C[(size_t)row * N + col] = v;
        }
    }
}

// ---------------- edge kernel: terms, leave-one-out products, tanh(ee), relu(esum2) ----------------
__global__ void edge_kernel(const float* __restrict__ global_emb,
                            const int* __restrict__ edge_nodes,
                            const int* __restrict__ edge_size,
                            const int* __restrict__ node_degree,
                            int E)
{
    int e = blockIdx.x;
    if (e >= E) return;
    int tid = threadIdx.x;   // 256

    __shared__ int   s_nodes[4];
    __shared__ float s_scale[4];
    __shared__ int   s_size;

    if (tid == 0) s_size = edge_size[e];
    if (tid < 4) {
        int n = edge_nodes[e * 4 + tid];
        s_nodes[tid] = n;
        int sz = edge_size[e];
        float a = (sz == 1) ? 1.0f : (sz <= 3 ? (1.0f / 3.0f) : 0.25f);
        s_scale[tid] = powf((float)node_degree[n], a);
    }
    __syncthreads();

    const int sz = s_size;
    const int k = 4 - sz;                         // 0,1,2
    const float invf = (sz == 3) ? 0.5f : (sz == 4 ? (1.0f / 6.0f) : 1.0f);

    if (tid < RANK) {
        const int r = tid;
        float g = global_emb[r];
        float gf = (k == 0) ? 1.0f : (k == 1 ? g : g * g);  // exact integer powers
        float t[4];
        #pragma unroll
        for (int s = 0; s < 4; s++)
            t[s] = (s < sz) ? s_scale[s] * g_emb_new[(size_t)s_nodes[s] * RANK + r] : 1.0f;
        float loo[4];
        loo[0] = t[1] * t[2] * t[3];
        loo[1] = t[0] * t[2] * t[3];
        loo[2] = t[0] * t[1] * t[3];
        loo[3] = t[0] * t[1] * t[2];
        float f = gf * invf;
        for (int s = 0; s < sz; s++)
            g_tee[((size_t)e * 4 + s) * RANK + r] = tanhf(loo[s] * f);
    }

    // esum2 (relu'd), 256 threads = 256 columns
    {
        float sum = 0.f;
        for (int s = 0; s < sz; s++)
            sum += g_emb_new2[(size_t)s_nodes[s] * OUTD + tid];
        g_esum2[(size_t)e * OUTD + tid] = fmaxf(sum, 0.f);
    }
}

// ---------------- incidence q-GEMM + scatter ----------------
// blockIdx.y in {0,1} selects a 128-column half of qW (32 KB static smem each).
__global__ __launch_bounds__(128)
void qscatter_kernel(const float* __restrict__ qW, const float* __restrict__ qb,
                     const int* __restrict__ inc_node,
                     const int* __restrict__ inc_edge,
                     const int* __restrict__ inc_slot,
                     int NINC)
{
    __shared__ float qWs[RANK * 128];
    const int tid = threadIdx.x;              // 0..127
    const int colBase = blockIdx.y * 128;
    const int col = colBase + tid;

    for (int i = tid; i < RANK * 128; i += 128) {
        int kk = i >> 7;
        int c  = i & 127;
        qWs[i] = qW[kk * OUTD + colBase + c];
    }
    __syncthreads();

    const float qbv = qb[col];

    for (int i = blockIdx.x; i < NINC; i += gridDim.x) {
        int e = inc_edge[i];
        int s = inc_slot[i];
        int n = inc_node[i];
        const float* tv = g_tee + ((size_t)e * 4 + s) * RANK;
        float out = qbv;
        #pragma unroll
        for (int kk = 0; kk < RANK; kk++)
            out += tv[kk] * qWs[kk * 128 + tid];       // tv[kk] is a warp-broadcast load
        out += g_esum2[(size_t)e * OUTD + col];
        atomicAdd(&g_nodeacc[(size_t)n * OUTD + col], out);
    }
}

// ---------------- misc ----------------
__global__ void zero_kernel(float* p, size_t n)
{
    size_t i = (size_t)blockIdx.x * blockDim.x + threadIdx.x;
    if (i < n) p[i] = 0.f;
}

__global__ void finalize_kernel(const int* __restrict__ node_degree,
                                float* __restrict__ out, int N)
{
    size_t i = (size_t)blockIdx.x * blockDim.x + threadIdx.x;
    if (i < (size_t)N * OUTD) {
        int n = (int)(i >> 8);
        float v = g_nodeacc[i] / (float)node_degree[n];
        out[i] = fmaxf(v, 0.f) + g_residual[i];
    }
}

// ---------------- launch ----------------
extern "C" void kernel_launch(void* const* d_in, const int* in_sizes, int n_in,
                              void* d_out, int out_size)
{
    const float* embedding  = (const float*)d_in[0];
    const float* global_emb = (const float*)d_in[1];
    const float* pW         = (const float*)d_in[2];
    const float* pb         = (const float*)d_in[3];
    const float* qW         = (const float*)d_in[4];
    const float* qb         = (const float*)d_in[5];
    const float* p2W1       = (const float*)d_in[6];
    const float* p2b1       = (const float*)d_in[7];
    const float* p2W2       = (const float*)d_in[8];
    const float* p2b2       = (const float*)d_in[9];
    const float* aW         = (const float*)d_in[10];
    const float* ab         = (const float*)d_in[11];
    const int*   edge_nodes = (const int*)d_in[12];
    // d_in[13] = edge_mask (bool) — derivable from edge_size, unused
    const int*   edge_size  = (const int*)d_in[14];
    const int*   node_deg   = (const int*)d_in[15];
    const int*   inc_node   = (const int*)d_in[16];
    const int*   inc_edge   = (const int*)d_in[17];
    const int*   inc_slot   = (const int*)d_in[18];

    const int N    = in_sizes[0] / FEAT;   // 30000
    const int E    = in_sizes[14];         // 60000
    const int NINC = in_sizes[16];         // ~180000

    float *p_emb_new, *p_hidden, *p_emb_new2, *p_residual, *p_nodeacc;
    cudaGetSymbolAddress((void**)&p_emb_new,  g_emb_new);
    cudaGetSymbolAddress((void**)&p_hidden,   g_hidden);
    cudaGetSymbolAddress((void**)&p_emb_new2, g_emb_new2);
    cudaGetSymbolAddress((void**)&p_residual, g_residual);
    cudaGetSymbolAddress((void**)&p_nodeacc,  g_nodeacc);

    // zero node accumulator
    {
        size_t n = (size_t)N * OUTD;
        zero_kernel<<<(unsigned)((n + 255) / 256), 256>>>(p_nodeacc, n);
    }

    dim3 blk(256);
    // G1: emb_new = embedding @ pW[:256] + (pb + pW[256,:])      [N x 64]
    {
        dim3 grid((RANK + BN - 1) / BN, (N + BM - 1) / BM);
        gemm_kernel<<<grid, blk>>>(embedding, pW, pb, pW + FEAT * RANK,
                                   p_emb_new, N, RANK, FEAT, 0);
    }
    // G2: hidden = relu(embedding @ p2W1[:256] + (p2b1 + p2W1[256,:]))   [N x 1024]
    {
        dim3 grid((HID + BN - 1) / BN, (N + BM - 1) / BM);
        gemm_kernel<<<grid, blk>>>(embedding, p2W1, p2b1, p2W1 + FEAT * HID,
                                   p_hidden, N, HID, FEAT, 1);
    }
    // G3: emb_new2 = hidden @ p2W2 + p2b2      [N x 256]
    {
        dim3 grid((OUTD + BN - 1) / BN, (N + BM - 1) / BM);
        gemm_kernel<<<grid, blk>>>(p_hidden, p2W2, p2b2, nullptr,
                                   p_emb_new2, N, OUTD, HID, 0);
    }
    // G4: residual = relu(embedding @ aW[:256] + (ab + aW[256,:]))    [N x 256]
    {
        dim3 grid((OUTD + BN - 1) / BN, (N + BM - 1) / BM);
        gemm_kernel<<<grid, blk>>>(embedding, aW, ab, aW + FEAT * OUTD,
                                   p_residual, N, OUTD, FEAT, 1);
    }

    // Edge-level: tanh(ee) and relu(esum2)
    edge_kernel<<<E, 256>>>(global_emb, edge_nodes, edge_size, node_deg, E);

    // Incidence-level q GEMM + atomic scatter into node accumulator
    {
        dim3 grid(2048, 2);
        qscatter_kernel<<<grid, 128>>>(qW, qb, inc_node, inc_edge, inc_slot, NINC);
    }

    // Finalize: relu(acc/deg) + residual
    {
        size_t n = (size_t)N * OUTD;
        finalize_kernel<<<(unsigned)((n + 255) / 256), 256>>>(node_deg, (float*)d_out, N);
    }
}

// round 3
// speedup vs baseline: 1.5950x; 1.5950x over previous
#include <cuda_runtime.h>
#include <math.h>
#include <stdint.h>

// Problem constants
#define NN   30000
#define NE   60000
#define FEAT 256
#define HID  1024
#define OUTD 256
#define RANK 64

// ---------------- scratch (device globals) ----------------
__device__ float g_emb_new [NN * RANK];
__device__ float g_hidden  [NN * HID];
__device__ float g_emb_new2[NN * OUTD];
__device__ float g_residual[NN * OUTD];
__device__ float g_tee     [NE * 4 * RANK];
__device__ float g_esum2   [NE * OUTD];
__device__ float g_nodeacc [NN * OUTD];
// transposed (K-major) weights, tf32-rounded: Wt[n][k]
__device__ float g_Wt1 [HID  * FEAT];
__device__ float g_Wt2 [OUTD * HID];
__device__ float g_WtA [OUTD * FEAT];
__device__ float g_WtP [RANK * FEAT];

// ---------------- helpers ----------------
__device__ __forceinline__ uint32_t smem_u32(const void* p) {
    uint32_t a;
    asm("{ .reg .u64 t; cvta.to.shared.u64 t, %1; cvt.u32.u64 %0, t; }" : "=r"(a) : "l"(p));
    return a;
}
__device__ __forceinline__ float tf32r(float x) {
    uint32_t u;
    asm("cvt.rna.tf32.f32 %0, %1;" : "=r"(u) : "f"(x));
    return __uint_as_float(u);
}
__device__ __forceinline__ uint32_t tf32b(float x) {
    uint32_t u;
    asm("cvt.rna.tf32.f32 %0, %1;" : "=r"(u) : "f"(x));
    return u;
}
__device__ __forceinline__ void cp16(uint32_t dst, const void* src, int szbytes) {
    asm volatile("cp.async.ca.shared.global [%0], [%1], 16, %2;"
                 :: "r"(dst), "l"(src), "r"(szbytes) : "memory");
}
#define CP_COMMIT() asm volatile("cp.async.commit_group;" ::: "memory")
#define CP_WAIT(n)  asm volatile("cp.async.wait_group %0;" :: "n"(n) : "memory")

// mma.sync m16n8k8 tf32: d += a*b (fp32 accumulate in place)
__device__ __forceinline__ void mma16n8k8(float* d, const uint32_t* a, const uint32_t* b) {
    asm volatile(
        "mma.sync.aligned.m16n8k8.row.col.f32.tf32.tf32.f32 "
        "{%0,%1,%2,%3}, {%4,%5,%6,%7}, {%8,%9}, {%0,%1,%2,%3};"
        : "+f"(d[0]), "+f"(d[1]), "+f"(d[2]), "+f"(d[3])
        : "r"(a[0]), "r"(a[1]), "r"(a[2]), "r"(a[3]), "r"(b[0]), "r"(b[1]));
}

// ---------------- weight transpose (+ tf32 round): Wt[n][k] = tf32(W[k][n]) ----------------
__global__ void transpose_tf32(const float* __restrict__ W, float* __restrict__ Wt, int K, int N)
{
    __shared__ float t[32][33];
    int n0 = blockIdx.x * 32, k0 = blockIdx.y * 32;
    for (int i = threadIdx.y; i < 32; i += 8)
        t[i][threadIdx.x] = W[(size_t)(k0 + i) * N + n0 + threadIdx.x];
    __syncthreads();
    for (int i = threadIdx.y; i < 32; i += 8)
        Wt[(size_t)(n0 + i) * K + k0 + threadIdx.x] = tf32r(t[threadIdx.x][i]);
}

// ---------------- tensor-core tf32 GEMM (mma.sync path, base-target safe) ----------------
// C[M,N] = act(A[M,K] @ Bt[N,K]^T + bias (+ biasRow))
// Block tile 128 x NT, K chunk 16, 8 warps (4 along M x 2 along N).
// Smem row stride 20 floats -> fragment loads hit 32 distinct banks (conflict-free).
template<int NT>
__global__ __launch_bounds__(256, 2)
void mma_gemm(const float* __restrict__ A, const float* __restrict__ Bt,
              const float* __restrict__ bias, const float* __restrict__ biasRow,
              float* __restrict__ C, int M, int N, int K, int doRelu)
{
    constexpr int ST = 20;                 // smem row stride (floats)
    constexpr int NTILES = NT / 16;        // 8-wide n-tiles per warp
    __shared__ float As[2][128 * ST];
    __shared__ float Bs[2][NT * ST];

    const int tid  = threadIdx.x;
    const int wid  = tid >> 5;
    const int lane = tid & 31;
    const int grp  = lane >> 2;            // 0..7
    const int tig  = lane & 3;             // 0..3
    const int warpM = (wid & 3) * 32;
    const int warpN = (wid >> 2) * (NT / 2);
    const int rowBase = blockIdx.y * 128;
    const int colBase = blockIdx.x * NT;

    float acc[2][NTILES][4];
    #pragma unroll
    for (int mt = 0; mt < 2; mt++)
        #pragma unroll
        for (int nt = 0; nt < NTILES; nt++)
            #pragma unroll
            for (int i = 0; i < 4; i++) acc[mt][nt][i] = 0.f;

    const uint32_t asm_base = smem_u32(&As[0][0]);
    const uint32_t bsm_base = smem_u32(&Bs[0][0]);

    // chunk loaders (cp.async, 16B each)
    auto loadChunk = [&](int c, int buf) {
        // A: 128 rows x 16 floats = 512 float4; 256 threads -> 2 each
        #pragma unroll
        for (int i = 0; i < 2; i++) {
            int idx = tid + (i << 8);
            int r = idx >> 2, f4 = idx & 3;
            int gr = rowBase + r;
            const float* src = A + (size_t)gr * K + (c << 4) + (f4 << 2);
            uint32_t dst = asm_base + (buf * 128 * ST + r * ST + (f4 << 2)) * 4;
            cp16(dst, src, gr < M ? 16 : 0);
        }
        // B: NT rows x 16 floats
        #pragma unroll
        for (int i = 0; i < NT / 64; i++) {
            int idx = tid + (i << 8);
            int r = idx >> 2, f4 = idx & 3;
            const float* src = Bt + (size_t)(colBase + r) * K + (c << 4) + (f4 << 2);
            uint32_t dst = bsm_base + (buf * NT * ST + r * ST + (f4 << 2)) * 4;
            cp16(dst, src, 16);
        }
        CP_COMMIT();
    };

    const int nch = K >> 4;
    loadChunk(0, 0);

    for (int c = 0; c < nch; ++c) {
        const int buf = c & 1;
        if (c + 1 < nch) { loadChunk(c + 1, buf ^ 1); CP_WAIT(1); }
        else             { CP_WAIT(0); }
        __syncthreads();

        const float* ab = &As[buf][0];
        const float* bb = &Bs[buf][0];
        #pragma unroll
        for (int ks = 0; ks < 2; ++ks) {
            const int kb = ks << 3;
            uint32_t afr[2][4];
            #pragma unroll
            for (int mt = 0; mt < 2; mt++) {
                int base = (warpM + mt * 16 + grp) * ST + kb + tig;
                afr[mt][0] = tf32b(ab[base]);
                afr[mt][1] = tf32b(ab[base + 8 * ST]);
                afr[mt][2] = tf32b(ab[base + 4]);
                afr[mt][3] = tf32b(ab[base + 8 * ST + 4]);
            }
            uint32_t bfr[NTILES][2];
            #pragma unroll
            for (int nt = 0; nt < NTILES; nt++) {
                int base = (warpN + nt * 8 + grp) * ST + kb + tig;
                bfr[nt][0] = __float_as_uint(bb[base]);
                bfr[nt][1] = __float_as_uint(bb[base + 4]);
            }
            #pragma unroll
            for (int mt = 0; mt < 2; mt++)
                #pragma unroll
                for (int nt = 0; nt < NTILES; nt++)
                    mma16n8k8(acc[mt][nt], afr[mt], bfr[nt]);
        }
        __syncthreads();
    }

    // epilogue: bias (+biasRow) + relu, float2 stores
    #pragma unroll
    for (int mt = 0; mt < 2; mt++) {
        #pragma unroll
        for (int nt = 0; nt < NTILES; nt++) {
            int col = colBase + warpN + nt * 8 + (tig << 1);
            float b0 = bias[col], b1 = bias[col + 1];
            if (biasRow) { b0 += biasRow[col]; b1 += biasRow[col + 1]; }
            #pragma unroll
            for (int h = 0; h < 2; h++) {
                int row = rowBase + warpM + mt * 16 + grp + h * 8;
                if (row < M) {
                    float v0 = acc[mt][nt][2 * h]     + b0;
                    float v1 = acc[mt][nt][2 * h + 1] + b1;
                    if (doRelu) { v0 = fmaxf(v0, 0.f); v1 = fmaxf(v1, 0.f); }
                    float2 v = make_float2(v0, v1);
                    *(float2*)(C + (size_t)row * N + col) = v;
                }
            }
        }
    }
}

// ---------------- edge kernel ----------------
__global__ void edge_kernel(const float* __restrict__ global_emb,
                            const int* __restrict__ edge_nodes,
                            const int* __restrict__ edge_size,
                            const int* __restrict__ node_degree,
                            int E)
{
    int e = blockIdx.x;
    if (e >= E) return;
    int tid = threadIdx.x;

    __shared__ int   s_nodes[4];
    __shared__ float s_scale[4];
    __shared__ int   s_size;

    if (tid == 0) s_size = edge_size[e];
    if (tid < 4) {
        int n = edge_nodes[e * 4 + tid];
        s_nodes[tid] = n;
        int sz = edge_size[e];
        float a = (sz == 1) ? 1.0f : (sz <= 3 ? (1.0f / 3.0f) : 0.25f);
        s_scale[tid] = powf((float)node_degree[n], a);
    }
    __syncthreads();

    const int sz = s_size;
    const int k = 4 - sz;
    const float invf = (sz == 3) ? 0.5f : (sz == 4 ? (1.0f / 6.0f) : 1.0f);

    if (tid < RANK) {
        const int r = tid;
        float g = global_emb[r];
        float gf = (k == 0) ? 1.0f : (k == 1 ? g : g * g);
        float t[4];
        #pragma unroll
        for (int s = 0; s < 4; s++)
            t[s] = (s < sz) ? s_scale[s] * g_emb_new[(size_t)s_nodes[s] * RANK + r] : 1.0f;
        float loo[4];
        loo[0] = t[1] * t[2] * t[3];
        loo[1] = t[0] * t[2] * t[3];
        loo[2] = t[0] * t[1] * t[3];
        loo[3] = t[0] * t[1] * t[2];
        float f = gf * invf;
        for (int s = 0; s < sz; s++)
            g_tee[((size_t)e * 4 + s) * RANK + r] = tanhf(loo[s] * f);
    }

    {
        float sum = 0.f;
        for (int s = 0; s < sz; s++)
            sum += g_emb_new2[(size_t)s_nodes[s] * OUTD + tid];
        g_esum2[(size_t)e * OUTD + tid] = fmaxf(sum, 0.f);
    }
}

// ---------------- incidence q-GEMM + scatter ----------------
__global__ __launch_bounds__(128)
void qscatter_kernel(const float* __restrict__ qW, const float* __restrict__ qb,
                     const int* __restrict__ inc_node,
                     const int* __restrict__ inc_edge,
                     const int* __restrict__ inc_slot,
                     int NINC)
{
    __shared__ float qWs[RANK * 128];
    const int tid = threadIdx.x;
    const int colBase = blockIdx.y * 128;
    const int col = colBase + tid;

    for (int i = tid; i < RANK * 128; i += 128) {
        int kk = i >> 7;
        int c  = i & 127;
        qWs[i] = qW[kk * OUTD + colBase + c];
    }
    __syncthreads();

    const float qbv = qb[col];

    for (int i = blockIdx.x; i < NINC; i += gridDim.x) {
        int e = inc_edge[i];
        int s = inc_slot[i];
        int n = inc_node[i];
        const float* tv = g_tee + ((size_t)e * 4 + s) * RANK;
        float out = qbv;
        #pragma unroll
        for (int kk = 0; kk < RANK; kk++)
            out += tv[kk] * qWs[kk * 128 + tid];
        out += g_esum2[(size_t)e * OUTD + col];
        atomicAdd(&g_nodeacc[(size_t)n * OUTD + col], out);
    }
}

// ---------------- misc ----------------
__global__ void zero_kernel(float* p, size_t n)
{
    size_t i = (size_t)blockIdx.x * blockDim.x + threadIdx.x;
    if (i < n) p[i] = 0.f;
}

__global__ void finalize_kernel(const int* __restrict__ node_degree,
                                float* __restrict__ out, int N)
{
    size_t i = (size_t)blockIdx.x * blockDim.x + threadIdx.x;
    if (i < (size_t)N * OUTD) {
        int n = (int)(i >> 8);
        float v = g_nodeacc[i] / (float)node_degree[n];
        out[i] = fmaxf(v, 0.f) + g_residual[i];
    }
}

// ---------------- launch ----------------
extern "C" void kernel_launch(void* const* d_in, const int* in_sizes, int n_in,
                              void* d_out, int out_size)
{
    const float* embedding  = (const float*)d_in[0];
    const float* global_emb = (const float*)d_in[1];
    const float* pW         = (const float*)d_in[2];
    const float* pb         = (const float*)d_in[3];
    const float* qW         = (const float*)d_in[4];
    const float* qb         = (const float*)d_in[5];
    const float* p2W1       = (const float*)d_in[6];
    const float* p2b1       = (const float*)d_in[7];
    const float* p2W2       = (const float*)d_in[8];
    const float* p2b2       = (const float*)d_in[9];
    const float* aW         = (const float*)d_in[10];
    const float* ab         = (const float*)d_in[11];
    const int*   edge_nodes = (const int*)d_in[12];
    const int*   edge_size  = (const int*)d_in[14];
    const int*   node_deg   = (const int*)d_in[15];
    const int*   inc_node   = (const int*)d_in[16];
    const int*   inc_edge   = (const int*)d_in[17];
    const int*   inc_slot   = (const int*)d_in[18];

    const int N    = in_sizes[0] / FEAT;
    const int E    = in_sizes[14];
    const int NINC = in_sizes[16];

    float *p_emb_new, *p_hidden, *p_emb_new2, *p_residual, *p_nodeacc;
    float *p_Wt1, *p_Wt2, *p_WtA, *p_WtP;
    cudaGetSymbolAddress((void**)&p_emb_new,  g_emb_new);
    cudaGetSymbolAddress((void**)&p_hidden,   g_hidden);
    cudaGetSymbolAddress((void**)&p_emb_new2, g_emb_new2);
    cudaGetSymbolAddress((void**)&p_residual, g_residual);
    cudaGetSymbolAddress((void**)&p_nodeacc,  g_nodeacc);
    cudaGetSymbolAddress((void**)&p_Wt1, g_Wt1);
    cudaGetSymbolAddress((void**)&p_Wt2, g_Wt2);
    cudaGetSymbolAddress((void**)&p_WtA, g_WtA);
    cudaGetSymbolAddress((void**)&p_WtP, g_WtP);

    // zero node accumulator
    {
        size_t n = (size_t)N * OUTD;
        zero_kernel<<<(unsigned)((n + 255) / 256), 256>>>(p_nodeacc, n);
    }

    // weight transposes (tf32-rounded), K-major [N x K]
    {
        dim3 b(32, 8);
        transpose_tf32<<<dim3(HID / 32,  FEAT / 32), b>>>(p2W1, p_Wt1, FEAT, HID);
        transpose_tf32<<<dim3(OUTD / 32, HID / 32),  b>>>(p2W2, p_Wt2, HID,  OUTD);
        transpose_tf32<<<dim3(OUTD / 32, FEAT / 32), b>>>(aW,   p_WtA, FEAT, OUTD);
        transpose_tf32<<<dim3(RANK / 32, FEAT / 32), b>>>(pW,   p_WtP, FEAT, RANK);
    }

    const int Mtiles = (N + 127) / 128;

    // G1: emb_new = embedding @ pW[:256] + (pb + pW[256,:])          [N x 64]
    mma_gemm<64><<<dim3(1, Mtiles), 256>>>(
        embedding, p_WtP, pb, pW + FEAT * RANK, p_emb_new, N, RANK, FEAT, 0);
    // G2: hidden = relu(embedding @ p2W1 + ...)                      [N x 1024]
    mma_gemm<128><<<dim3(HID / 128, Mtiles), 256>>>(
        embedding, p_Wt1, p2b1, p2W1 + FEAT * HID, p_hidden, N, HID, FEAT, 1);
    // G3: emb_new2 = hidden @ p2W2 + p2b2                            [N x 256]
    mma_gemm<128><<<dim3(OUTD / 128, Mtiles), 256>>>(
        p_hidden, p_Wt2, p2b2, nullptr, p_emb_new2, N, OUTD, HID, 0);
    // G4: residual = relu(embedding @ aW + ...)                      [N x 256]
    mma_gemm<128><<<dim3(OUTD / 128, Mtiles), 256>>>(
        embedding, p_WtA, ab, aW + FEAT * OUTD, p_residual, N, OUTD, FEAT, 1);

    // edge-level
    edge_kernel<<<E, 256>>>(global_emb, edge_nodes, edge_size, node_deg, E);

    // incidence q GEMM + scatter
    {
        dim3 grid(2048, 2);
        qscatter_kernel<<<grid, 128>>>(qW, qb, inc_node, inc_edge, inc_slot, NINC);
    }

    // finalize
    {
        size_t n = (size_t)N * OUTD;
        finalize_kernel<<<(unsigned)((n + 255) / 256), 256>>>(node_deg, (float*)d_out, N);
    }
}

// round 4
// speedup vs baseline: 3.2863x; 2.0604x over previous
#include <cuda_runtime.h>
#include <math.h>
#include <stdint.h>

// Problem constants
#define NN   30000
#define NE   60000
#define FEAT 256
#define HID  1024
#define OUTD 256
#define RANK 64

// ---------------- scratch (device globals) ----------------
__device__ float g_emb_new [NN * RANK];
__device__ float g_hidden  [NN * HID];
__device__ float g_emb_new2[NN * OUTD];
__device__ float g_residual[NN * OUTD];
__device__ float g_tee     [NE * 4 * RANK];
__device__ float g_esum2   [NE * OUTD];
__device__ float g_nodeacc [NN * OUTD];   // sum of relu(esum2) per node
__device__ float g_accR    [NN * RANK];   // sum of tanh(ee) per node
__device__ int   g_offs    [NN + 1];
__device__ int   g_cursor  [NN];
__device__ int   g_csr     [NE * 4];
// transposed (K-major) weights, tf32-rounded: Wt[n][k]
__device__ float g_Wt1 [HID  * FEAT];
__device__ float g_Wt2 [OUTD * HID];
__device__ float g_WtA [OUTD * FEAT];
__device__ float g_WtP [RANK * FEAT];
__device__ float g_WtQ [OUTD * RANK];

// ---------------- helpers ----------------
__device__ __forceinline__ uint32_t smem_u32(const void* p) {
    uint32_t a;
    asm("{ .reg .u64 t; cvta.to.shared.u64 t, %1; cvt.u32.u64 %0, t; }" : "=r"(a) : "l"(p));
    return a;
}
__device__ __forceinline__ float tf32r(float x) {
    uint32_t u;
    asm("cvt.rna.tf32.f32 %0, %1;" : "=r"(u) : "f"(x));
    return __uint_as_float(u);
}
__device__ __forceinline__ uint32_t tf32b(float x) {
    uint32_t u;
    asm("cvt.rna.tf32.f32 %0, %1;" : "=r"(u) : "f"(x));
    return u;
}
__device__ __forceinline__ void cp16(uint32_t dst, const void* src, int szbytes) {
    asm volatile("cp.async.ca.shared.global [%0], [%1], 16, %2;"
                 :: "r"(dst), "l"(src), "r"(szbytes) : "memory");
}
#define CP_COMMIT() asm volatile("cp.async.commit_group;" ::: "memory")
#define CP_WAIT(n)  asm volatile("cp.async.wait_group %0;" :: "n"(n) : "memory")

__device__ __forceinline__ void mma16n8k8(float* d, const uint32_t* a, const uint32_t* b) {
    asm volatile(
        "mma.sync.aligned.m16n8k8.row.col.f32.tf32.tf32.f32 "
        "{%0,%1,%2,%3}, {%4,%5,%6,%7}, {%8,%9}, {%0,%1,%2,%3};"
        : "+f"(d[0]), "+f"(d[1]), "+f"(d[2]), "+f"(d[3])
        : "r"(a[0]), "r"(a[1]), "r"(a[2]), "r"(a[3]), "r"(b[0]), "r"(b[1]));
}

// ---------------- weight transpose (+ tf32 round): Wt[n][k] = tf32(W[k][n]) ----------------
__global__ void transpose_tf32(const float* __restrict__ W, float* __restrict__ Wt, int K, int N)
{
    __shared__ float t[32][33];
    int n0 = blockIdx.x * 32, k0 = blockIdx.y * 32;
    for (int i = threadIdx.y; i < 32; i += 8)
        t[i][threadIdx.x] = W[(size_t)(k0 + i) * N + n0 + threadIdx.x];
    __syncthreads();
    for (int i = threadIdx.y; i < 32; i += 8)
        Wt[(size_t)(n0 + i) * K + k0 + threadIdx.x] = tf32r(t[threadIdx.x][i]);
}

// ---------------- CSR build: exclusive scan of node_degree + fill ----------------
__global__ void scan_offsets(const int* __restrict__ deg, int* __restrict__ offs,
                             int* __restrict__ cursor, int N)
{
    __shared__ int carry;
    __shared__ int buf[1024];
    int tid = threadIdx.x;
    if (tid == 0) carry = 0;
    __syncthreads();
    for (int base = 0; base < N; base += 1024) {
        int i = base + tid;
        int x = (i < N) ? deg[i] : 0;
        buf[tid] = x;
        __syncthreads();
        #pragma unroll
        for (int off = 1; off < 1024; off <<= 1) {
            int v = (tid >= off) ? buf[tid - off] : 0;
            __syncthreads();
            buf[tid] += v;
            __syncthreads();
        }
        int incl = buf[tid];
        if (i < N) { offs[i] = carry + incl - x; cursor[i] = 0; }
        int total = buf[1023];
        __syncthreads();
        if (tid == 0) carry += total;
        __syncthreads();
    }
    if (tid == 0) offs[N] = carry;
}

__global__ void csr_fill(const int* __restrict__ inc_node, const int* __restrict__ inc_edge,
                         const int* __restrict__ inc_slot, int NINC)
{
    int i = blockIdx.x * blockDim.x + threadIdx.x;
    if (i < NINC) {
        int n = inc_node[i];
        int p = atomicAdd(&g_cursor[n], 1);
        g_csr[g_offs[n] + p] = (inc_edge[i] << 2) | inc_slot[i];
    }
}

// ---------------- tensor-core tf32 GEMM (mma.sync) ----------------
// C[M,N] = epilogue(A[M,K] @ Bt[N,K]^T)
// mode 0: + bias (+biasRow)          mode 1: relu(+bias(+biasRow))
// mode 2: relu((acc + addSrc)/deg + bias) + resid   (final output fusion)
template<int NT>
__global__ __launch_bounds__(256, 2)
void mma_gemm(const float* __restrict__ A, const float* __restrict__ Bt,
              const float* __restrict__ bias, const float* __restrict__ biasRow,
              float* __restrict__ C, int M, int N, int K, int mode,
              const float* __restrict__ addSrc, const float* __restrict__ resid,
              const int* __restrict__ degv)
{
    constexpr int ST = 20;
    constexpr int NTILES = NT / 16;
    __shared__ float As[2][128 * ST];
    __shared__ float Bs[2][NT * ST];

    const int tid  = threadIdx.x;
    const int wid  = tid >> 5;
    const int lane = tid & 31;
    const int grp  = lane >> 2;
    const int tig  = lane & 3;
    const int warpM = (wid & 3) * 32;
    const int warpN = (wid >> 2) * (NT / 2);
    const int rowBase = blockIdx.y * 128;
    const int colBase = blockIdx.x * NT;

    float acc[2][NTILES][4];
    #pragma unroll
    for (int mt = 0; mt < 2; mt++)
        #pragma unroll
        for (int nt = 0; nt < NTILES; nt++)
            #pragma unroll
            for (int i = 0; i < 4; i++) acc[mt][nt][i] = 0.f;

    const uint32_t asm_base = smem_u32(&As[0][0]);
    const uint32_t bsm_base = smem_u32(&Bs[0][0]);

    auto loadChunk = [&](int c, int buf) {
        #pragma unroll
        for (int i = 0; i < 2; i++) {
            int idx = tid + (i << 8);
            int r = idx >> 2, f4 = idx & 3;
            int gr = rowBase + r;
            const float* src = A + (size_t)gr * K + (c << 4) + (f4 << 2);
            uint32_t dst = asm_base + (buf * 128 * ST + r * ST + (f4 << 2)) * 4;
            cp16(dst, src, gr < M ? 16 : 0);
        }
        #pragma unroll
        for (int i = 0; i < NT / 64; i++) {
            int idx = tid + (i << 8);
            int r = idx >> 2, f4 = idx & 3;
            const float* src = Bt + (size_t)(colBase + r) * K + (c << 4) + (f4 << 2);
            uint32_t dst = bsm_base + (buf * NT * ST + r * ST + (f4 << 2)) * 4;
            cp16(dst, src, 16);
        }
        CP_COMMIT();
    };

    const int nch = K >> 4;
    loadChunk(0, 0);

    for (int c = 0; c < nch; ++c) {
        const int buf = c & 1;
        if (c + 1 < nch) { loadChunk(c + 1, buf ^ 1); CP_WAIT(1); }
        else             { CP_WAIT(0); }
        __syncthreads();

        const float* ab = &As[buf][0];
        const float* bb = &Bs[buf][0];
        #pragma unroll
        for (int ks = 0; ks < 2; ++ks) {
            const int kb = ks << 3;
            uint32_t afr[2][4];
            #pragma unroll
            for (int mt = 0; mt < 2; mt++) {
                int base = (warpM + mt * 16 + grp) * ST + kb + tig;
                afr[mt][0] = tf32b(ab[base]);
                afr[mt][1] = tf32b(ab[base + 8 * ST]);
                afr[mt][2] = tf32b(ab[base + 4]);
                afr[mt][3] = tf32b(ab[base + 8 * ST + 4]);
            }
            uint32_t bfr[NTILES][2];
            #pragma unroll
            for (int nt = 0; nt < NTILES; nt++) {
                int base = (warpN + nt * 8 + grp) * ST + kb + tig;
                bfr[nt][0] = __float_as_uint(bb[base]);
                bfr[nt][1] = __float_as_uint(bb[base + 4]);
            }
            #pragma unroll
            for (int mt = 0; mt < 2; mt++)
                #pragma unroll
                for (int nt = 0; nt < NTILES; nt++)
                    mma16n8k8(acc[mt][nt], afr[mt], bfr[nt]);
        }
        __syncthreads();
    }

    #pragma unroll
    for (int mt = 0; mt < 2; mt++) {
        #pragma unroll
        for (int nt = 0; nt < NTILES; nt++) {
            int col = colBase + warpN + nt * 8 + (tig << 1);
            float b0 = bias[col], b1 = bias[col + 1];
            if (mode != 2 && biasRow) { b0 += biasRow[col]; b1 += biasRow[col + 1]; }
            #pragma unroll
            for (int h = 0; h < 2; h++) {
                int row = rowBase + warpM + mt * 16 + grp + h * 8;
                if (row >= M) continue;
                float v0 = acc[mt][nt][2 * h];
                float v1 = acc[mt][nt][2 * h + 1];
                if (mode == 2) {
                    float rd = 1.0f / (float)degv[row];
                    size_t base = (size_t)row * N + col;
                    v0 = fmaxf((v0 + addSrc[base])     * rd + b0, 0.f) + resid[base];
                    v1 = fmaxf((v1 + addSrc[base + 1]) * rd + b1, 0.f) + resid[base + 1];
                } else {
                    v0 += b0; v1 += b1;
                    if (mode == 1) { v0 = fmaxf(v0, 0.f); v1 = fmaxf(v1, 0.f); }
                }
                *(float2*)(C + (size_t)row * N + col) = make_float2(v0, v1);
            }
        }
    }
}

// ---------------- edge kernel: tanh(ee) per (edge,slot), relu(esum2) per edge ----------------
__global__ void edge_kernel(const float* __restrict__ global_emb,
                            const int* __restrict__ edge_nodes,
                            const int* __restrict__ edge_size,
                            const int* __restrict__ node_degree,
                            int E)
{
    int e = blockIdx.x;
    if (e >= E) return;
    int tid = threadIdx.x;

    __shared__ int   s_nodes[4];
    __shared__ float s_scale[4];
    __shared__ int   s_size;

    if (tid == 0) s_size = edge_size[e];
    if (tid < 4) {
        int n = edge_nodes[e * 4 + tid];
        s_nodes[tid] = n;
        int sz = edge_size[e];
        float a = (sz == 1) ? 1.0f : (sz <= 3 ? (1.0f / 3.0f) : 0.25f);
        s_scale[tid] = powf((float)node_degree[n], a);
    }
    __syncthreads();

    const int sz = s_size;
    const int k = 4 - sz;
    const float invf = (sz == 3) ? 0.5f : (sz == 4 ? (1.0f / 6.0f) : 1.0f);

    if (tid < RANK) {
        const int r = tid;
        float g = global_emb[r];
        float gf = (k == 0) ? 1.0f : (k == 1 ? g : g * g);
        float t[4];
        #pragma unroll
        for (int s = 0; s < 4; s++)
            t[s] = (s < sz) ? s_scale[s] * g_emb_new[(size_t)s_nodes[s] * RANK + r] : 1.0f;
        float loo[4];
        loo[0] = t[1] * t[2] * t[3];
        loo[1] = t[0] * t[2] * t[3];
        loo[2] = t[0] * t[1] * t[3];
        loo[3] = t[0] * t[1] * t[2];
        float f = gf * invf;
        for (int s = 0; s < sz; s++)
            g_tee[((size_t)e * 4 + s) * RANK + r] = tanhf(loo[s] * f);
    }

    {
        float sum = 0.f;
        for (int s = 0; s < sz; s++)
            sum += g_emb_new2[(size_t)s_nodes[s] * OUTD + tid];
        g_esum2[(size_t)e * OUTD + tid] = fmaxf(sum, 0.f);
    }
}

// ---------------- node-major gather: acc256 = sum relu(esum2), accR = sum tanh(ee) ----------------
__global__ __launch_bounds__(256)
void node_gather()
{
    int n = blockIdx.x;
    int tid = threadIdx.x;
    int s0 = g_offs[n], s1 = g_offs[n + 1];
    float acc = 0.f;
    float accr = 0.f;
    for (int j = s0; j < s1; ++j) {
        int code = g_csr[j];
        int e = code >> 2, s = code & 3;
        acc += g_esum2[(size_t)e * OUTD + tid];
        if (tid < RANK) accr += g_tee[((size_t)e * 4 + s) * RANK + tid];
    }
    g_nodeacc[(size_t)n * OUTD + tid] = acc;
    if (tid < RANK) g_accR[(size_t)n * RANK + tid] = accr;
}

// ---------------- launch ----------------
extern "C" void kernel_launch(void* const* d_in, const int* in_sizes, int n_in,
                              void* d_out, int out_size)
{
    const float* embedding  = (const float*)d_in[0];
    const float* global_emb = (const float*)d_in[1];
    const float* pW         = (const float*)d_in[2];
    const float* pb         = (const float*)d_in[3];
    const float* qW         = (const float*)d_in[4];
    const float* qb         = (const float*)d_in[5];
    const float* p2W1       = (const float*)d_in[6];
    const float* p2b1       = (const float*)d_in[7];
    const float* p2W2       = (const float*)d_in[8];
    const float* p2b2       = (const float*)d_in[9];
    const float* aW         = (const float*)d_in[10];
    const float* ab         = (const float*)d_in[11];
    const int*   edge_nodes = (const int*)d_in[12];
    const int*   edge_size  = (const int*)d_in[14];
    const int*   node_deg   = (const int*)d_in[15];
    const int*   inc_node   = (const int*)d_in[16];
    const int*   inc_edge   = (const int*)d_in[17];
    const int*   inc_slot   = (const int*)d_in[18];

    const int N    = in_sizes[0] / FEAT;
    const int E    = in_sizes[14];
    const int NINC = in_sizes[16];

    float *p_emb_new, *p_hidden, *p_emb_new2, *p_residual, *p_nodeacc, *p_accR;
    float *p_Wt1, *p_Wt2, *p_WtA, *p_WtP, *p_WtQ;
    int *p_offs;
    cudaGetSymbolAddress((void**)&p_emb_new,  g_emb_new);
    cudaGetSymbolAddress((void**)&p_hidden,   g_hidden);
    cudaGetSymbolAddress((void**)&p_emb_new2, g_emb_new2);
    cudaGetSymbolAddress((void**)&p_residual, g_residual);
    cudaGetSymbolAddress((void**)&p_nodeacc,  g_nodeacc);
    cudaGetSymbolAddress((void**)&p_accR,     g_accR);
    cudaGetSymbolAddress((void**)&p_offs,     g_offs);
    cudaGetSymbolAddress((void**)&p_Wt1, g_Wt1);
    cudaGetSymbolAddress((void**)&p_Wt2, g_Wt2);
    cudaGetSymbolAddress((void**)&p_WtA, g_WtA);
    cudaGetSymbolAddress((void**)&p_WtP, g_WtP);
    cudaGetSymbolAddress((void**)&p_WtQ, g_WtQ);

    int *p_cursor;
    cudaGetSymbolAddress((void**)&p_cursor, g_cursor);

    // weight transposes (tf32-rounded), K-major [N x K]
    {
        dim3 b(32, 8);
        transpose_tf32<<<dim3(HID / 32,  FEAT / 32), b>>>(p2W1, p_Wt1, FEAT, HID);
        transpose_tf32<<<dim3(OUTD / 32, HID / 32),  b>>>(p2W2, p_Wt2, HID,  OUTD);
        transpose_tf32<<<dim3(OUTD / 32, FEAT / 32), b>>>(aW,   p_WtA, FEAT, OUTD);
        transpose_tf32<<<dim3(RANK / 32, FEAT / 32), b>>>(pW,   p_WtP, FEAT, RANK);
        transpose_tf32<<<dim3(OUTD / 32, RANK / 32), b>>>(qW,   p_WtQ, RANK, OUTD);
    }

    // CSR build
    scan_offsets<<<1, 1024>>>(node_deg, p_offs, p_cursor, N);
    csr_fill<<<(NINC + 255) / 256, 256>>>(inc_node, inc_edge, inc_slot, NINC);

    const int Mtiles = (N + 127) / 128;

    // G1: emb_new = embedding @ pW[:256] + (pb + pW[256,:])          [N x 64]
    mma_gemm<64><<<dim3(1, Mtiles), 256>>>(
        embedding, p_WtP, pb, pW + FEAT * RANK, p_emb_new, N, RANK, FEAT, 0,
        nullptr, nullptr, nullptr);
    // G2: hidden = relu(embedding @ p2W1 + ...)                      [N x 1024]
    mma_gemm<128><<<dim3(HID / 128, Mtiles), 256>>>(
        embedding, p_Wt1, p2b1, p2W1 + FEAT * HID, p_hidden, N, HID, FEAT, 1,
        nullptr, nullptr, nullptr);
    // G3: emb_new2 = hidden @ p2W2 + p2b2                            [N x 256]
    mma_gemm<128><<<dim3(OUTD / 128, Mtiles), 256>>>(
        p_hidden, p_Wt2, p2b2, nullptr, p_emb_new2, N, OUTD, HID, 0,
        nullptr, nullptr, nullptr);
    // G4: residual = relu(embedding @ aW + ...)                      [N x 256]
    mma_gemm<128><<<dim3(OUTD / 128, Mtiles), 256>>>(
        embedding, p_WtA, ab, aW + FEAT * OUTD, p_residual, N, OUTD, FEAT, 1,
        nullptr, nullptr, nullptr);

    // edge-level: tanh(ee) + relu(esum2)
    edge_kernel<<<E, 256>>>(global_emb, edge_nodes, edge_size, node_deg, E);

    // node-major gather (no atomics)
    node_gather<<<N, 256>>>();

    // final fused GEMM: out = relu((accR@qW^T + acc256)/deg + qb) + residual
    mma_gemm<128><<<dim3(OUTD / 128, Mtiles), 256>>>(
        p_accR, p_WtQ, qb, nullptr, (float*)d_out, N, OUTD, RANK, 2,
        p_nodeacc, p_residual, node_deg);
}

// round 5
// speedup vs baseline: 4.1638x; 1.2670x over previous
#include <cuda_runtime.h>
#include <math.h>
#include <stdint.h>

// Problem constants
#define NN   30000
#define NE   60000
#define FEAT 256
#define HID  1024
#define OUTD 256
#define RANK 64

// ---------------- scratch (device globals) ----------------
__device__ float g_embR    [NN * FEAT];   // tf32-rounded embedding
__device__ float g_emb_new [NN * RANK];
__device__ float g_hidden  [NN * HID];    // stored tf32-rounded
__device__ float g_emb_new2[NN * OUTD];
__device__ float g_residual[NN * OUTD];
__device__ float g_tee     [NE * 4 * RANK];
__device__ float g_esum2   [NE * OUTD];
__device__ float g_nodeacc [NN * OUTD];
__device__ float g_accR    [NN * RANK];   // stored tf32-rounded
__device__ int   g_offs    [NN + 1];
__device__ int   g_cursor  [NN];
__device__ int   g_csr     [NE * 4];
// transposed (K-major) weights, tf32-rounded: Wt[n][k]
__device__ float g_Wt1 [HID  * FEAT];
__device__ float g_Wt2 [OUTD * HID];
__device__ float g_WtA [OUTD * FEAT];
__device__ float g_WtP [RANK * FEAT];
__device__ float g_WtQ [OUTD * RANK];

// ---------------- helpers ----------------
__device__ __forceinline__ uint32_t smem_u32(const void* p) {
    uint32_t a;
    asm("{ .reg .u64 t; cvta.to.shared.u64 t, %1; cvt.u32.u64 %0, t; }" : "=r"(a) : "l"(p));
    return a;
}
__device__ __forceinline__ float tf32r(float x) {
    uint32_t u;
    asm("cvt.rna.tf32.f32 %0, %1;" : "=r"(u) : "f"(x));
    return __uint_as_float(u);
}
__device__ __forceinline__ void cp16(uint32_t dst, const void* src, int szbytes) {
    asm volatile("cp.async.ca.shared.global [%0], [%1], 16, %2;"
                 :: "r"(dst), "l"(src), "r"(szbytes) : "memory");
}
#define CP_COMMIT() asm volatile("cp.async.commit_group;" ::: "memory")
#define CP_WAIT(n)  asm volatile("cp.async.wait_group %0;" :: "n"(n) : "memory")

__device__ __forceinline__ void mma16n8k8(float* d, const uint32_t* a, const uint32_t* b) {
    asm volatile(
        "mma.sync.aligned.m16n8k8.row.col.f32.tf32.tf32.f32 "
        "{%0,%1,%2,%3}, {%4,%5,%6,%7}, {%8,%9}, {%0,%1,%2,%3};"
        : "+f"(d[0]), "+f"(d[1]), "+f"(d[2]), "+f"(d[3])
        : "r"(a[0]), "r"(a[1]), "r"(a[2]), "r"(a[3]), "r"(b[0]), "r"(b[1]));
}

// ---------------- embedding tf32 pre-round ----------------
__global__ void round_emb(const float4* __restrict__ src, float4* __restrict__ dst, int n4)
{
    int i = blockIdx.x * blockDim.x + threadIdx.x;
    if (i < n4) {
        float4 v = src[i];
        v.x = tf32r(v.x); v.y = tf32r(v.y); v.z = tf32r(v.z); v.w = tf32r(v.w);
        dst[i] = v;
    }
}

// ---------------- batched weight transpose (+ tf32 round): Wt[n][k] = tf32(W[k][n]) ----------------
struct TJob { const float* W; float* Wt; int K; int N; int tstart; };
__global__ void transpose5(TJob j0, TJob j1, TJob j2, TJob j3, TJob j4)
{
    __shared__ float t[32][33];
    int bx = blockIdx.x;
    TJob p;
    if      (bx >= j4.tstart) p = j4;
    else if (bx >= j3.tstart) p = j3;
    else if (bx >= j2.tstart) p = j2;
    else if (bx >= j1.tstart) p = j1;
    else                      p = j0;
    int tt = bx - p.tstart;
    int tiles_n = p.N >> 5;
    int n0 = (tt % tiles_n) * 32, k0 = (tt / tiles_n) * 32;
    for (int i = threadIdx.y; i < 32; i += 8)
        t[i][threadIdx.x] = p.W[(size_t)(k0 + i) * p.N + n0 + threadIdx.x];
    __syncthreads();
    for (int i = threadIdx.y; i < 32; i += 8)
        p.Wt[(size_t)(n0 + i) * p.K + k0 + threadIdx.x] = tf32r(t[threadIdx.x][i]);
}

// ---------------- CSR offsets: single-block coarsened exclusive scan ----------------
__global__ __launch_bounds__(1024)
void scan_offsets(const int* __restrict__ deg, int* __restrict__ offs,
                  int* __restrict__ cursor, int N)
{
    const int tid = threadIdx.x;
    const int CE = (N + 1023) / 1024;      // elems per thread (30 for N=30000)
    int start = tid * CE;
    int vals[32];
    int local = 0;
    for (int j = 0; j < CE; j++) {
        int i = start + j;
        int v = (i < N) ? deg[i] : 0;
        vals[j] = local;
        local += v;
    }
    __shared__ int warpsum[32];
    int lane = tid & 31, w = tid >> 5;
    int x = local;
    #pragma unroll
    for (int o = 1; o < 32; o <<= 1) { int y = __shfl_up_sync(~0u, x, o); if (lane >= o) x += y; }
    if (lane == 31) warpsum[w] = x;
    __syncthreads();
    if (w == 0) {
        int s = warpsum[lane];
        #pragma unroll
        for (int o = 1; o < 32; o <<= 1) { int y = __shfl_up_sync(~0u, s, o); if (lane >= o) s += y; }
        warpsum[lane] = s;
    }
    __syncthreads();
    int base = x - local + (w > 0 ? warpsum[w - 1] : 0);
    for (int j = 0; j < CE; j++) {
        int i = start + j;
        if (i < N) { offs[i] = base + vals[j]; cursor[i] = 0; }
    }
    if (tid == 1023) offs[N] = base + local;
}

__global__ void csr_fill(const int* __restrict__ inc_node, const int* __restrict__ inc_edge,
                         const int* __restrict__ inc_slot, int NINC)
{
    int i = blockIdx.x * blockDim.x + threadIdx.x;
    if (i < NINC) {
        int n = inc_node[i];
        int p = atomicAdd(&g_cursor[n], 1);
        g_csr[g_offs[n] + p] = (inc_edge[i] << 2) | inc_slot[i];
    }
}

// ---------------- tensor-core tf32 GEMM (mma.sync, K-chunk 32, pre-rounded A) ----------------
// mode bits: 0/1 -> (+bias(+biasRow)) / relu(...); 2 -> relu((acc+addSrc)/deg + bias)+resid;
// bit 4 (|4): tf32-round stored values.
template<int NT>
__global__ __launch_bounds__(256, 2)
void mma_gemm(const float* __restrict__ A, const float* __restrict__ Bt,
              const float* __restrict__ bias, const float* __restrict__ biasRow,
              float* __restrict__ C, int M, int N, int K, int mode,
              const float* __restrict__ addSrc, const float* __restrict__ resid,
              const int* __restrict__ degv)
{
    constexpr int ST = 36;                 // 32 + 4 pad (bank-conflict-free fragments)
    constexpr int NTILES = NT / 16;
    extern __shared__ float dyn[];
    float* Asm = dyn;                      // 2 bufs x 128 x ST
    float* Bsm = dyn + 2 * 128 * ST;       // 2 bufs x NT x ST

    const int tid  = threadIdx.x;
    const int wid  = tid >> 5;
    const int lane = tid & 31;
    const int grp  = lane >> 2;
    const int tig  = lane & 3;
    const int warpM = (wid & 3) * 32;
    const int warpN = (wid >> 2) * (NT / 2);
    const int rowBase = blockIdx.y * 128;
    const int colBase = blockIdx.x * NT;
    const int baseMode = mode & 3;
    const bool roundOut = (mode & 4) != 0;

    float acc[2][NTILES][4];
    #pragma unroll
    for (int mt = 0; mt < 2; mt++)
        #pragma unroll
        for (int nt = 0; nt < NTILES; nt++)
            #pragma unroll
            for (int i = 0; i < 4; i++) acc[mt][nt][i] = 0.f;

    const uint32_t asm_base = smem_u32(Asm);
    const uint32_t bsm_base = smem_u32(Bsm);

    auto loadChunk = [&](int c, int buf) {
        // A: 128 rows x 32 floats = 1024 float4
        #pragma unroll
        for (int i = 0; i < 4; i++) {
            int idx = tid + (i << 8);
            int r = idx >> 3, f4 = idx & 7;
            int gr = rowBase + r;
            const float* src = A + (size_t)gr * K + (c << 5) + (f4 << 2);
            uint32_t dst = asm_base + (buf * 128 * ST + r * ST + (f4 << 2)) * 4;
            cp16(dst, src, gr < M ? 16 : 0);
        }
        // B: NT rows x 32 floats
        #pragma unroll
        for (int i = 0; i < NT / 32; i++) {
            int idx = tid + (i << 8);
            int r = idx >> 3, f4 = idx & 7;
            const float* src = Bt + (size_t)(colBase + r) * K + (c << 5) + (f4 << 2);
            uint32_t dst = bsm_base + (buf * NT * ST + r * ST + (f4 << 2)) * 4;
            cp16(dst, src, 16);
        }
        CP_COMMIT();
    };

    const int nch = K >> 5;
    loadChunk(0, 0);

    for (int c = 0; c < nch; ++c) {
        const int buf = c & 1;
        if (c + 1 < nch) { loadChunk(c + 1, buf ^ 1); CP_WAIT(1); }
        else             { CP_WAIT(0); }
        __syncthreads();

        const float* ab = Asm + buf * 128 * ST;
        const float* bb = Bsm + buf * NT * ST;
        #pragma unroll
        for (int ks = 0; ks < 4; ++ks) {
            const int kb = ks << 3;
            uint32_t afr[2][4];
            #pragma unroll
            for (int mt = 0; mt < 2; mt++) {
                int base = (warpM + mt * 16 + grp) * ST + kb + tig;
                afr[mt][0] = __float_as_uint(ab[base]);
                afr[mt][1] = __float_as_uint(ab[base + 8 * ST]);
                afr[mt][2] = __float_as_uint(ab[base + 4]);
                afr[mt][3] = __float_as_uint(ab[base + 8 * ST + 4]);
            }
            uint32_t bfr[NTILES][2];
            #pragma unroll
            for (int nt = 0; nt < NTILES; nt++) {
                int base = (warpN + nt * 8 + grp) * ST + kb + tig;
                bfr[nt][0] = __float_as_uint(bb[base]);
                bfr[nt][1] = __float_as_uint(bb[base + 4]);
            }
            #pragma unroll
            for (int mt = 0; mt < 2; mt++)
                #pragma unroll
                for (int nt = 0; nt < NTILES; nt++)
                    mma16n8k8(acc[mt][nt], afr[mt], bfr[nt]);
        }
        __syncthreads();
    }

    #pragma unroll
    for (int mt = 0; mt < 2; mt++) {
        #pragma unroll
        for (int nt = 0; nt < NTILES; nt++) {
            int col = colBase + warpN + nt * 8 + (tig << 1);
            float b0 = bias[col], b1 = bias[col + 1];
            if (baseMode != 2 && biasRow) { b0 += biasRow[col]; b1 += biasRow[col + 1]; }
            #pragma unroll
            for (int h = 0; h < 2; h++) {
                int row = rowBase + warpM + mt * 16 + grp + h * 8;
                if (row >= M) continue;
                float v0 = acc[mt][nt][2 * h];
                float v1 = acc[mt][nt][2 * h + 1];
                if (baseMode == 2) {
                    float rd = 1.0f / (float)degv[row];
                    size_t base = (size_t)row * N + col;
                    v0 = fmaxf((v0 + addSrc[base])     * rd + b0, 0.f) + resid[base];
                    v1 = fmaxf((v1 + addSrc[base + 1]) * rd + b1, 0.f) + resid[base + 1];
                } else {
                    v0 += b0; v1 += b1;
                    if (baseMode == 1) { v0 = fmaxf(v0, 0.f); v1 = fmaxf(v1, 0.f); }
                }
                if (roundOut) { v0 = tf32r(v0); v1 = tf32r(v1); }
                *(float2*)(C + (size_t)row * N + col) = make_float2(v0, v1);
            }
        }
    }
}

// ---------------- edge kernel: 2 edges per 256-thread block ----------------
__global__ __launch_bounds__(256)
void edge_kernel(const float* __restrict__ global_emb,
                 const int* __restrict__ edge_nodes,
                 const int* __restrict__ edge_size,
                 const int* __restrict__ node_degree,
                 int E)
{
    __shared__ int   s_nodes[2][4];
    __shared__ float s_scale[2][4];
    __shared__ int   s_size[2];

    const int half = threadIdx.x >> 7;
    const int lt   = threadIdx.x & 127;
    const int e    = blockIdx.x * 2 + half;
    const bool active = (e < E);

    if (active && lt < 4) {
        int sz = edge_size[e];
        if (lt == 0) s_size[half] = sz;
        int n = edge_nodes[e * 4 + lt];
        s_nodes[half][lt] = n;
        float a = (sz == 1) ? 1.0f : (sz <= 3 ? (1.0f / 3.0f) : 0.25f);
        s_scale[half][lt] = powf((float)node_degree[n], a);
    }
    __syncthreads();
    if (!active) return;

    const int sz = s_size[half];
    const int k = 4 - sz;
    const float invf = (sz == 3) ? 0.5f : (sz == 4 ? (1.0f / 6.0f) : 1.0f);

    if (lt < RANK) {
        const int r = lt;
        float g = global_emb[r];
        float gf = (k == 0) ? 1.0f : (k == 1 ? g : g * g);
        float t[4];
        #pragma unroll
        for (int s = 0; s < 4; s++)
            t[s] = (s < sz) ? s_scale[half][s] * g_emb_new[(size_t)s_nodes[half][s] * RANK + r] : 1.0f;
        float loo[4];
        loo[0] = t[1] * t[2] * t[3];
        loo[1] = t[0] * t[2] * t[3];
        loo[2] = t[0] * t[1] * t[3];
        loo[3] = t[0] * t[1] * t[2];
        float f = gf * invf;
        for (int s = 0; s < sz; s++)
            g_tee[((size_t)e * 4 + s) * RANK + r] = tanhf(loo[s] * f);
    }

    {
        float sum0 = 0.f, sum1 = 0.f;
        for (int s = 0; s < sz; s++) {
            const float* row = g_emb_new2 + (size_t)s_nodes[half][s] * OUTD;
            sum0 += row[lt];
            sum1 += row[lt + 128];
        }
        g_esum2[(size_t)e * OUTD + lt]       = fmaxf(sum0, 0.f);
        g_esum2[(size_t)e * OUTD + lt + 128] = fmaxf(sum1, 0.f);
    }
}

// ---------------- node-major gather ----------------
__global__ __launch_bounds__(256)
void node_gather()
{
    int n = blockIdx.x;
    int tid = threadIdx.x;
    int s0 = g_offs[n], s1 = g_offs[n + 1];
    float acc = 0.f;
    float accr = 0.f;
    for (int j = s0; j < s1; ++j) {
        int code = g_csr[j];
        int e = code >> 2, s = code & 3;
        acc += g_esum2[(size_t)e * OUTD + tid];
        if (tid < RANK) accr += g_tee[((size_t)e * 4 + s) * RANK + tid];
    }
    g_nodeacc[(size_t)n * OUTD + tid] = acc;
    if (tid < RANK) g_accR[(size_t)n * RANK + tid] = tf32r(accr);
}

// ---------------- launch ----------------
extern "C" void kernel_launch(void* const* d_in, const int* in_sizes, int n_in,
                              void* d_out, int out_size)
{
    const float* embedding  = (const float*)d_in[0];
    const float* global_emb = (const float*)d_in[1];
    const float* pW         = (const float*)d_in[2];
    const float* pb         = (const float*)d_in[3];
    const float* qW         = (const float*)d_in[4];
    const float* qb         = (const float*)d_in[5];
    const float* p2W1       = (const float*)d_in[6];
    const float* p2b1       = (const float*)d_in[7];
    const float* p2W2       = (const float*)d_in[8];
    const float* p2b2       = (const float*)d_in[9];
    const float* aW         = (const float*)d_in[10];
    const float* ab         = (const float*)d_in[11];
    const int*   edge_nodes = (const int*)d_in[12];
    const int*   edge_size  = (const int*)d_in[14];
    const int*   node_deg   = (const int*)d_in[15];
    const int*   inc_node   = (const int*)d_in[16];
    const int*   inc_edge   = (const int*)d_in[17];
    const int*   inc_slot   = (const int*)d_in[18];

    const int N    = in_sizes[0] / FEAT;
    const int E    = in_sizes[14];
    const int NINC = in_sizes[16];

    float *p_embR, *p_emb_new, *p_hidden, *p_emb_new2, *p_residual, *p_nodeacc, *p_accR;
    float *p_Wt1, *p_Wt2, *p_WtA, *p_WtP, *p_WtQ;
    int *p_offs, *p_cursor;
    cudaGetSymbolAddress((void**)&p_embR,     g_embR);
    cudaGetSymbolAddress((void**)&p_emb_new,  g_emb_new);
    cudaGetSymbolAddress((void**)&p_hidden,   g_hidden);
    cudaGetSymbolAddress((void**)&p_emb_new2, g_emb_new2);
    cudaGetSymbolAddress((void**)&p_residual, g_residual);
    cudaGetSymbolAddress((void**)&p_nodeacc,  g_nodeacc);
    cudaGetSymbolAddress((void**)&p_accR,     g_accR);
    cudaGetSymbolAddress((void**)&p_offs,     g_offs);
    cudaGetSymbolAddress((void**)&p_cursor,   g_cursor);
    cudaGetSymbolAddress((void**)&p_Wt1, g_Wt1);
    cudaGetSymbolAddress((void**)&p_Wt2, g_Wt2);
    cudaGetSymbolAddress((void**)&p_WtA, g_WtA);
    cudaGetSymbolAddress((void**)&p_WtP, g_WtP);
    cudaGetSymbolAddress((void**)&p_WtQ, g_WtQ);

    const int SMEM128 = 2 * 128 * 36 * 4 * 2;        // 73728
    const int SMEM64  = (2 * 128 * 36 + 2 * 64 * 36) * 4;  // 55296
    cudaFuncSetAttribute(mma_gemm<128>, cudaFuncAttributeMaxDynamicSharedMemorySize, SMEM128);
    cudaFuncSetAttribute(mma_gemm<64>,  cudaFuncAttributeMaxDynamicSharedMemorySize, SMEM64);

    // launch 0: pre-round embedding to tf32
    {
        int n4 = N * FEAT / 4;
        round_emb<<<(n4 + 255) / 256, 256>>>((const float4*)embedding, (float4*)p_embR, n4);
    }

    // launch 1: all 5 weight transposes in one kernel
    {
        TJob j0 = { p2W1, p_Wt1, FEAT, HID,  0   };   // 256 tiles
        TJob j1 = { p2W2, p_Wt2, HID,  OUTD, 256 };   // 256
        TJob j2 = { aW,   p_WtA, FEAT, OUTD, 512 };   // 64
        TJob j3 = { pW,   p_WtP, FEAT, RANK, 576 };   // 16
        TJob j4 = { qW,   p_WtQ, RANK, OUTD, 592 };   // 16 -> total 608
        transpose5<<<608, dim3(32, 8)>>>(j0, j1, j2, j3, j4);
    }

    // launch 2-3: CSR build
    scan_offsets<<<1, 1024>>>(node_deg, p_offs, p_cursor, N);
    csr_fill<<<(NINC + 255) / 256, 256>>>(inc_node, inc_edge, inc_slot, NINC);

    const int Mtiles = (N + 127) / 128;

    // launch 4: G1 emb_new = embR @ pW^T + (pb + pW[256,:])          [N x 64]
    mma_gemm<64><<<dim3(1, Mtiles), 256, SMEM64>>>(
        p_embR, p_WtP, pb, pW + FEAT * RANK, p_emb_new, N, RANK, FEAT, 0,
        nullptr, nullptr, nullptr);
    // launch 5 (ncu target): G2 hidden = relu(embR @ p2W1 + ...), stored tf32  [N x 1024]
    mma_gemm<128><<<dim3(HID / 128, Mtiles), 256, SMEM128>>>(
        p_embR, p_Wt1, p2b1, p2W1 + FEAT * HID, p_hidden, N, HID, FEAT, 1 | 4,
        nullptr, nullptr, nullptr);
    // G3: emb_new2 = hidden @ p2W2 + p2b2                            [N x 256]
    mma_gemm<128><<<dim3(OUTD / 128, Mtiles), 256, SMEM128>>>(
        p_hidden, p_Wt2, p2b2, nullptr, p_emb_new2, N, OUTD, HID, 0,
        nullptr, nullptr, nullptr);
    // G4: residual = relu(embR @ aW + ...)                           [N x 256]
    mma_gemm<128><<<dim3(OUTD / 128, Mtiles), 256, SMEM128>>>(
        p_embR, p_WtA, ab, aW + FEAT * OUTD, p_residual, N, OUTD, FEAT, 1,
        nullptr, nullptr, nullptr);

    // edge-level: tanh(ee) + relu(esum2), 2 edges per block
    edge_kernel<<<(E + 1) / 2, 256>>>(global_emb, edge_nodes, edge_size, node_deg, E);

    // node-major gather (no atomics)
    node_gather<<<N, 256>>>();

    // final fused GEMM: out = relu((accR@qW^T + acc256)/deg + qb) + residual
    mma_gemm<128><<<dim3(OUTD / 128, Mtiles), 256, SMEM128>>>(
        p_accR, p_WtQ, qb, nullptr, (float*)d_out, N, OUTD, RANK, 2,
        p_nodeacc, p_residual, node_deg);
}